// round 8
// baseline (speedup 1.0000x reference)
#include <cuda_runtime.h>
#include <cuda_bf16.h>
#include <cuda_fp16.h>
#include <math.h>
#include <stdint.h>

// Problem dims
#define Bb   4
#define Nn   2048
#define DIMd 768
#define Hh   12
#define DHd  64
#define MLPm 3072
#define Ll   2
#define Mrows (Bb*Nn)   // 8192

// ---------------- scratch (device globals: allocation-free) ----------------
__device__ float  g_x [Mrows*DIMd];
__device__ __half g_xn[Mrows*DIMd];
__device__ float  g_q [Mrows*DIMd];
__device__ float  g_kv[Mrows*2*DIMd];
__device__ __half g_ao[Mrows*DIMd];
__device__ __half g_h [Mrows*MLPm];
#define WPK_LAYER (DIMd*DIMd + DIMd*2*DIMd + DIMd*DIMd + DIMd*MLPm + MLPm*DIMd)
__device__ __half g_wpk[DIMd*DIMd + 2*WPK_LAYER];

// ---------------- PTX helpers ----------------------------------------------
__device__ __forceinline__ unsigned cvta_s(const void* p) {
    return (unsigned)__cvta_generic_to_shared(p);
}
#define CPA16(dst, src) asm volatile("cp.async.cg.shared.global [%0], [%1], 16;" :: "r"(dst), "l"(src))
#define CPCOMMIT()      asm volatile("cp.async.commit_group;")
#define CPWAIT1()       asm volatile("cp.async.wait_group 1;")
#define CPWAIT0()       asm volatile("cp.async.wait_group 0;")

__device__ __forceinline__ float tf32r(float x) {
    float r;
    asm("cvt.rna.tf32.f32 %0, %1;" : "=f"(r) : "f"(x));
    return r;
}

// tf32 mma (attention)
__device__ __forceinline__ void mma8(float& c0, float& c1, float& c2, float& c3,
                                     float a0, float a1, float a2, float a3,
                                     float b0, float b1) {
    asm volatile(
        "mma.sync.aligned.m16n8k8.row.col.f32.tf32.tf32.f32 "
        "{%0,%1,%2,%3},{%4,%5,%6,%7},{%8,%9},{%0,%1,%2,%3};"
        : "+f"(c0), "+f"(c1), "+f"(c2), "+f"(c3)
        : "r"(__float_as_uint(a0)), "r"(__float_as_uint(a1)),
          "r"(__float_as_uint(a2)), "r"(__float_as_uint(a3)),
          "r"(__float_as_uint(b0)), "r"(__float_as_uint(b1)));
}

// fp16 mma m16n8k16 (GEMMs)
__device__ __forceinline__ void mma16(float& c0, float& c1, float& c2, float& c3,
                                      uint32_t a0, uint32_t a1, uint32_t a2, uint32_t a3,
                                      uint32_t b0, uint32_t b1) {
    asm volatile(
        "mma.sync.aligned.m16n8k16.row.col.f32.f16.f16.f32 "
        "{%0,%1,%2,%3},{%4,%5,%6,%7},{%8,%9},{%0,%1,%2,%3};"
        : "+f"(c0), "+f"(c1), "+f"(c2), "+f"(c3)
        : "r"(a0), "r"(a1), "r"(a2), "r"(a3), "r"(b0), "r"(b1));
}

// ---------------- single-launch weight pack (fp16 B-fragment layout) -------
// Per (kb = 32-k block, grp = 8-col group): 256 halves at
//   P + (kb*(Nc/8)+grp)*256 + ks*128 + lane*4, lane = 4*g + t:
//   { W[kb*32+ks*16+2t][n8+g], W[..2t+1][..], W[..2t+8][..], W[..2t+9][..] }
struct PackDesc { const float* src; __half* dst; int K; int Nc; };
struct PackTable { PackDesc d[11]; };

__global__ void __launch_bounds__(256) pack_all(PackTable tab)
{
    __shared__ float Ws[32][257];
    PackDesc pd = tab.d[blockIdx.y];
    int tn = pd.Nc >> 8;
    int total = tn * (pd.K >> 5);
    int bx = blockIdx.x;
    if (bx >= total) return;
    int n0 = (bx % tn) << 8, kb = bx / tn;
    const float* W = pd.src;
    int Nc = pd.Nc;
    int tid = threadIdx.x;
#pragma unroll
    for (int p = 0; p < 8; p++) {
        int idx = tid + p * 256;
        int r = idx >> 6, c4 = (idx & 63) << 2;
        float4 v = *(const float4*)(W + (size_t)(kb * 32 + r) * Nc + n0 + c4);
        Ws[r][c4] = v.x; Ws[r][c4 + 1] = v.y;
        Ws[r][c4 + 2] = v.z; Ws[r][c4 + 3] = v.w;
    }
    __syncthreads();
    __half* out = pd.dst + ((size_t)kb * (Nc >> 3) + (n0 >> 3)) * 256;
#pragma unroll
    for (int p = 0; p < 8; p++) {
        int q = tid + p * 256;        // 2048 chunks of 4 halves
        int lg = q >> 6;              // local group 0..31
        int w  = q & 63;
        int ks = w >> 5;
        int l  = w & 31;
        int g = l >> 2, t = l & 3;
        int n = lg * 8 + g;
        int kbase = ks * 16;
        __half2 p0 = __floats2half2_rn(Ws[kbase + 2 * t][n], Ws[kbase + 2 * t + 1][n]);
        __half2 p1 = __floats2half2_rn(Ws[kbase + 2 * t + 8][n], Ws[kbase + 2 * t + 9][n]);
        __half* dst = out + ((size_t)lg * 2 + ks) * 128 + l * 4;
        *(__half2*)(dst)     = p0;
        *(__half2*)(dst + 2) = p1;
    }
}

// ---------------- LayerNorm (OH: output half for GEMM A operands) ----------
template<int OH>
__global__ void __launch_bounds__(256) ln_k(const float* __restrict__ X,
                                            const float* __restrict__ g,
                                            void* __restrict__ Yv)
{
    int row = blockIdx.x;
    const float* x = X + (size_t)row * DIMd;
    int tid = threadIdx.x;
    float v[3]; float s = 0.f, sq = 0.f;
#pragma unroll
    for (int i = 0; i < 3; i++) {
        v[i] = x[tid + i * 256];
        s += v[i]; sq += v[i] * v[i];
    }
#pragma unroll
    for (int o = 16; o; o >>= 1) {
        s  += __shfl_xor_sync(~0u, s, o);
        sq += __shfl_xor_sync(~0u, sq, o);
    }
    __shared__ float red[2][8];
    int w = tid >> 5, lane = tid & 31;
    if (lane == 0) { red[0][w] = s; red[1][w] = sq; }
    __syncthreads();
    s = 0.f; sq = 0.f;
#pragma unroll
    for (int j = 0; j < 8; j++) { s += red[0][j]; sq += red[1][j]; }
    float mean = s * (1.f / DIMd);
    float var  = sq * (1.f / DIMd) - mean * mean;
    float rstd = rsqrtf(var + 1e-5f);
#pragma unroll
    for (int i = 0; i < 3; i++) {
        int c = tid + i * 256;
        float o = (v[i] - mean) * rstd * g[c];
        if (OH) ((__half*)Yv)[(size_t)row * DIMd + c] = __float2half_rn(o);
        else    ((float*)Yv)[(size_t)row * DIMd + c] = o;
    }
}

// ---------------- fp16 TC GEMM, tile 128x128, 3-stage cp.async -------------
// 8 warps: 4(m) x 2(n), each 32x64, k-step 32 (2 x k16 mma).
// A half row-major (pre-rounded), B half fragment-packed.
// EPI: 0 none(float out), 1 +bias(float), 2 gelu(x+b)->HALF out,
//      3 +res(float), 4 +bias+res(float)
#define A_LD 40                       // halves per row (32 data + 8 pad)
#define A_HALVES (128*A_LD)           // 5120
#define B_HALVES (16*256)             // 4096
#define STG_HALVES (A_HALVES + B_HALVES)   // 9216
#define GEMM_SMEM (3*STG_HALVES*2)    // 55296 B

template<int EPI>
__global__ void __launch_bounds__(256, 2) gemm_tc(const __half* __restrict__ A,
                                                  const __half* __restrict__ Wpk,
                                                  const float* __restrict__ bias,
                                                  const float* __restrict__ res,
                                                  void* __restrict__ Cv,
                                                  int K, int Nc)
{
    extern __shared__ __half smh[];
    uint32_t smem_base = cvta_s(smh);
    int tid = threadIdx.x;
    int warp = tid >> 5, lane = tid & 31;
    int g = lane >> 2, t = lane & 3;
    int wm = (warp >> 1) * 32;
    int warpn = warp & 1;
    int m0 = blockIdx.y * 128, n0 = blockIdx.x * 128;

    const __half* Ag = A + (size_t)m0 * K;
    const __half* Bg = Wpk + (size_t)(n0 >> 3) * 256;
    size_t bstride = (size_t)(Nc >> 3) * 256;   // halves per k-block

    float acc[2][8][4];
#pragma unroll
    for (int a = 0; a < 2; a++)
#pragma unroll
        for (int b = 0; b < 8; b++)
#pragma unroll
            for (int c = 0; c < 4; c++) acc[a][b][c] = 0.f;

    auto loadA = [&](int s, int kb) {
        uint32_t dst = smem_base + (uint32_t)(s * STG_HALVES) * 2;
#pragma unroll
        for (int p = 0; p < 2; p++) {
            int q = tid + p * 256;       // 512 chunks of 16B
            int m = q >> 2, j = q & 3;
            CPA16(dst + (uint32_t)m * (A_LD * 2) + (uint32_t)j * 16,
                  Ag + (size_t)m * K + kb * 32 + j * 8);
        }
    };
    auto loadB = [&](int s, int kb) {
        uint32_t dst = smem_base + (uint32_t)(s * STG_HALVES + A_HALVES) * 2;
        const __half* src = Bg + (size_t)kb * bstride;
#pragma unroll
        for (int p = 0; p < 2; p++) {
            int q = tid + p * 256;       // 512 chunks of 16B
            CPA16(dst + (uint32_t)q * 16, src + (size_t)q * 8);
        }
    };

    int niter = K >> 5;
    loadA(0, 0); loadB(0, 0); CPCOMMIT();
    loadA(1, 1); loadB(1, 1); CPCOMMIT();

    for (int it = 0; it < niter; it++) {
        if (it + 1 < niter) { CPWAIT1(); } else { CPWAIT0(); }
        __syncthreads();
        if (it + 2 < niter) {
            loadA((it + 2) % 3, it + 2);
            loadB((it + 2) % 3, it + 2);
            CPCOMMIT();
        }
        const __half* As = smh + (it % 3) * STG_HALVES;
        const __half* Bs = As + A_HALVES;

#pragma unroll
        for (int ks = 0; ks < 2; ks++) {
            uint32_t af[2][4], bf[8][2];
#pragma unroll
            for (int mt = 0; mt < 2; mt++) {
                int r = wm + mt * 16 + g;
                af[mt][0] = *(const uint32_t*)&As[r * A_LD + ks * 16 + 2 * t];
                af[mt][1] = *(const uint32_t*)&As[(r + 8) * A_LD + ks * 16 + 2 * t];
                af[mt][2] = *(const uint32_t*)&As[r * A_LD + ks * 16 + 2 * t + 8];
                af[mt][3] = *(const uint32_t*)&As[(r + 8) * A_LD + ks * 16 + 2 * t + 8];
            }
#pragma unroll
            for (int nt = 0; nt < 8; nt++) {
                uint2 bb = *(const uint2*)&Bs[(((warpn * 8 + nt) * 2 + ks) << 7) + lane * 4];
                bf[nt][0] = bb.x; bf[nt][1] = bb.y;
            }
#pragma unroll
            for (int mt = 0; mt < 2; mt++)
#pragma unroll
                for (int nt = 0; nt < 8; nt++)
                    mma16(acc[mt][nt][0], acc[mt][nt][1],
                          acc[mt][nt][2], acc[mt][nt][3],
                          af[mt][0], af[mt][1], af[mt][2], af[mt][3],
                          bf[nt][0], bf[nt][1]);
        }
        __syncthreads();
    }

    int wn = warpn * 64;
    float* C = (float*)Cv;
    __half* Ch = (__half*)Cv;
#pragma unroll
    for (int mt = 0; mt < 2; mt++) {
        int row = m0 + wm + mt * 16 + g;
#pragma unroll
        for (int nt = 0; nt < 8; nt++) {
            int col = n0 + wn + nt * 8 + 2 * t;
            float v0 = acc[mt][nt][0], v1 = acc[mt][nt][1];
            float v2 = acc[mt][nt][2], v3 = acc[mt][nt][3];
            if (EPI == 1 || EPI == 2 || EPI == 4) {
                float b0 = bias[col], b1 = bias[col + 1];
                v0 += b0; v1 += b1; v2 += b0; v3 += b1;
            }
            size_t o0 = (size_t)row * Nc + col;
            size_t o1 = (size_t)(row + 8) * Nc + col;
            if (EPI == 2) {
                v0 = 0.5f * v0 * (1.0f + erff(v0 * 0.70710678118654752f));
                v1 = 0.5f * v1 * (1.0f + erff(v1 * 0.70710678118654752f));
                v2 = 0.5f * v2 * (1.0f + erff(v2 * 0.70710678118654752f));
                v3 = 0.5f * v3 * (1.0f + erff(v3 * 0.70710678118654752f));
                *(__half2*)&Ch[o0] = __floats2half2_rn(v0, v1);
                *(__half2*)&Ch[o1] = __floats2half2_rn(v2, v3);
            } else {
                if (EPI == 3 || EPI == 4) {
                    float2 r0 = *(const float2*)(res + o0);
                    float2 r1 = *(const float2*)(res + o1);
                    v0 += r0.x; v1 += r0.y; v2 += r1.x; v3 += r1.y;
                }
                *(float2*)(C + o0) = make_float2(v0, v1);
                *(float2*)(C + o1) = make_float2(v2, v3);
            }
        }
    }
}

// -------- QK RMSNorm + 2D RoPE + tf32 round (also rounds V) ---------------
__global__ void __launch_bounds__(256) qkrope_k(float* __restrict__ Q,
                                                float* __restrict__ KV,
                                                const float* __restrict__ qg,
                                                const float* __restrict__ kg,
                                                const int* __restrict__ h_idx,
                                                const int* __restrict__ w_idx)
{
    int warp = blockIdx.x * 8 + (threadIdx.x >> 5);
    int lane = threadIdx.x & 31;
    int grp = warp / (Mrows * Hh);       // 0=Q, 1=K, 2=V
    int rid = warp - grp * (Mrows * Hh);
    int bn = rid / Hh;
    int h  = rid % Hh;

    if (grp == 2) {  // V: round only
        float* ptr = KV + (size_t)bn * 2 * DIMd + DIMd + h * DHd;
        ptr[lane]      = tf32r(ptr[lane]);
        ptr[lane + 32] = tf32r(ptr[lane + 32]);
        return;
    }

    float* ptr;
    const float* g;
    if (grp == 0) { ptr = Q  + (size_t)bn * DIMd     + h * DHd; g = qg + h * DHd; }
    else          { ptr = KV + (size_t)bn * 2 * DIMd + h * DHd; g = kg + h * DHd; }

    float v1 = ptr[lane], v2 = ptr[lane + 32];
    float ss = v1 * v1 + v2 * v2;
#pragma unroll
    for (int o = 16; o; o >>= 1) ss += __shfl_xor_sync(~0u, ss, o);
    float sc = 8.0f / fmaxf(sqrtf(ss), 1e-12f);
    v1 = v1 * sc * g[lane];
    v2 = v2 * sc * g[lane + 32];

    int f = lane & 15;
    float invf = exp2f(-(float)f * (13.287712379549449f / 16.0f));
    float th1 = (float)h_idx[bn] * invf;
    float th2 = (float)w_idx[bn] * invf;
    float p1 = __shfl_xor_sync(~0u, v1, 16);
    float p2 = __shfl_xor_sync(~0u, v2, 16);
    float rh1 = (lane < 16) ? -p1 : p1;
    float rh2 = (lane < 16) ? -p2 : p2;
    ptr[lane]      = tf32r(v1 * cosf(th1) + rh1 * sinf(th1));
    ptr[lane + 32] = tf32r(v2 * cosf(th2) + rh2 * sinf(th2));
}

// ---------------- TF32 TC flash attention (half output) --------------------
#define KS_LD 68
#define VS_LD 72
#define PS_LD 68
#define ATT_SMEM ((2*64*KS_LD + 2*64*VS_LD + 128*PS_LD) * 4)   // 106496

__global__ void __launch_bounds__(256) attn_tc(const float* __restrict__ Q,
                                               const float* __restrict__ KV,
                                               const int* __restrict__ lengths,
                                               __half* __restrict__ O)
{
    extern __shared__ float sm[];
    float* KsB = sm;
    float* VsB = KsB + 2 * 64 * KS_LD;
    float* Ps  = VsB + 2 * 64 * VS_LD;

    int b = blockIdx.z, h = blockIdx.y, q0 = blockIdx.x * 128;
    int tid = threadIdx.x;
    int warp = tid >> 5, lane = tid & 31;
    int g = lane >> 2, t = lane & 3;
    int wq = warp * 16;

    const float* Qg = Q  + ((size_t)b * Nn + q0) * DIMd + h * DHd;
    const float* Kg = KV + ((size_t)b * Nn) * 2 * DIMd + h * DHd;
    int len = lengths[b];

    float qf[8][4];
    {
        const float* r0 = Qg + (size_t)(wq + g) * DIMd;
        const float* r1 = r0 + 8 * DIMd;
#pragma unroll
        for (int kk = 0; kk < 8; kk++) {
            qf[kk][0] = r0[kk * 8 + t];
            qf[kk][1] = r1[kk * 8 + t];
            qf[kk][2] = r0[kk * 8 + t + 4];
            qf[kk][3] = r1[kk * 8 + t + 4];
        }
    }

    float Oa[8][4];
    float mrow[2], lrow[2];
#pragma unroll
    for (int n = 0; n < 8; n++)
#pragma unroll
        for (int c = 0; c < 4; c++) Oa[n][c] = 0.f;
    mrow[0] = mrow[1] = -1e30f;
    lrow[0] = lrow[1] = 0.f;

    int ntiles = (len + 63) >> 6;

    auto loadKV = [&](int buf, int kt) {
        float* Kd = KsB + buf * 64 * KS_LD;
        float* Vd = VsB + buf * 64 * VS_LD;
#pragma unroll
        for (int p = 0; p < 4; p++) {
            int idx = tid + p * 256;
            int r = idx >> 4, c = (idx & 15) << 2;
            const float* kp = Kg + (size_t)(kt * 64 + r) * (2 * DIMd) + c;
            CPA16(cvta_s(Kd + r * KS_LD + c), kp);
            CPA16(cvta_s(Vd + r * VS_LD + c), kp + DIMd);
        }
    };

    loadKV(0, 0); CPCOMMIT();

    for (int kt = 0; kt < ntiles; kt++) {
        CPWAIT0();
        __syncthreads();
        if (kt + 1 < ntiles) { loadKV((kt + 1) & 1, kt + 1); CPCOMMIT(); }
        const float* Ks = KsB + (kt & 1) * 64 * KS_LD;
        const float* Vs = VsB + (kt & 1) * 64 * VS_LD;

        float S[8][4];
#pragma unroll
        for (int n = 0; n < 8; n++)
#pragma unroll
            for (int c = 0; c < 4; c++) S[n][c] = 0.f;

#pragma unroll
        for (int kk = 0; kk < 8; kk++) {
            float bf[8][2];
#pragma unroll
            for (int nt = 0; nt < 8; nt++) {
                int key = nt * 8 + g;
                bf[nt][0] = Ks[key * KS_LD + kk * 8 + t];
                bf[nt][1] = Ks[key * KS_LD + kk * 8 + t + 4];
            }
#pragma unroll
            for (int nt = 0; nt < 8; nt++)
                mma8(S[nt][0], S[nt][1], S[nt][2], S[nt][3],
                     qf[kk][0], qf[kk][1], qf[kk][2], qf[kk][3],
                     bf[nt][0], bf[nt][1]);
        }

#pragma unroll
        for (int nt = 0; nt < 8; nt++) {
            int kc = kt * 64 + nt * 8 + 2 * t;
            if (kc >= len)     { S[nt][0] = -1e30f; S[nt][2] = -1e30f; }
            if (kc + 1 >= len) { S[nt][1] = -1e30f; S[nt][3] = -1e30f; }
        }

#pragma unroll
        for (int half = 0; half < 2; half++) {
            int i0 = half * 2, i1 = half * 2 + 1;
            float rm = -1e30f;
#pragma unroll
            for (int nt = 0; nt < 8; nt++)
                rm = fmaxf(rm, fmaxf(S[nt][i0], S[nt][i1]));
            rm = fmaxf(rm, __shfl_xor_sync(~0u, rm, 1));
            rm = fmaxf(rm, __shfl_xor_sync(~0u, rm, 2));
            float mn = fmaxf(mrow[half], rm);
            float rs = 0.f;
#pragma unroll
            for (int nt = 0; nt < 8; nt++) {
                S[nt][i0] = __expf(S[nt][i0] - mn);
                S[nt][i1] = __expf(S[nt][i1] - mn);
                rs += S[nt][i0] + S[nt][i1];
            }
            rs += __shfl_xor_sync(~0u, rs, 1);
            rs += __shfl_xor_sync(~0u, rs, 2);
            float corr = __expf(mrow[half] - mn);
            lrow[half] = lrow[half] * corr + rs;
            mrow[half] = mn;
#pragma unroll
            for (int nt = 0; nt < 8; nt++) {
                Oa[nt][i0] *= corr;
                Oa[nt][i1] *= corr;
            }
        }

        {
            int r = wq + g;
#pragma unroll
            for (int nt = 0; nt < 8; nt++) {
                int c = nt * 8 + 2 * t;
                *(float2*)&Ps[r * PS_LD + c] =
                    make_float2(tf32r(S[nt][0]), tf32r(S[nt][1]));
                *(float2*)&Ps[(r + 8) * PS_LD + c] =
                    make_float2(tf32r(S[nt][2]), tf32r(S[nt][3]));
            }
        }
        __syncwarp();

#pragma unroll
        for (int kk = 0; kk < 8; kk++) {
            float af[4], bf[8][2];
            af[0] = Ps[(wq + g) * PS_LD + kk * 8 + t];
            af[1] = Ps[(wq + 8 + g) * PS_LD + kk * 8 + t];
            af[2] = Ps[(wq + g) * PS_LD + kk * 8 + t + 4];
            af[3] = Ps[(wq + 8 + g) * PS_LD + kk * 8 + t + 4];
#pragma unroll
            for (int nt = 0; nt < 8; nt++) {
                int c = nt * 8 + g;
                bf[nt][0] = Vs[(kk * 8 + t) * VS_LD + c];
                bf[nt][1] = Vs[(kk * 8 + t + 4) * VS_LD + c];
            }
#pragma unroll
            for (int nt = 0; nt < 8; nt++)
                mma8(Oa[nt][0], Oa[nt][1], Oa[nt][2], Oa[nt][3],
                     af[0], af[1], af[2], af[3],
                     bf[nt][0], bf[nt][1]);
        }
    }

    {
        int row0 = q0 + wq + g;
        float inv0 = 1.0f / lrow[0];
        float inv1 = 1.0f / lrow[1];
#pragma unroll
        for (int nt = 0; nt < 8; nt++) {
            int col = h * DHd + nt * 8 + 2 * t;
            size_t o0 = ((size_t)b * Nn + row0) * DIMd + col;
            size_t o1 = ((size_t)b * Nn + row0 + 8) * DIMd + col;
            *(__half2*)&O[o0] = __floats2half2_rn(Oa[nt][0] * inv0, Oa[nt][1] * inv0);
            *(__half2*)&O[o1] = __floats2half2_rn(Oa[nt][2] * inv1, Oa[nt][3] * inv1);
        }
    }
}

// ---------------- mask tail writer -----------------------------------------
__global__ void mask_k(const int* __restrict__ lengths, float* __restrict__ out)
{
    int i = blockIdx.x * blockDim.x + threadIdx.x;
    if (i < Bb * Nn) {
        int b = i / Nn, n = i % Nn;
        out[i] = (n < lengths[b]) ? 1.0f : 0.0f;
    }
}

// ---------------- host orchestration ---------------------------------------
extern "C" void kernel_launch(void* const* d_in, const int* in_sizes, int n_in,
                              void* d_out, int out_size)
{
    const float* patches    = (const float*)d_in[0];
    const float* pe_ln1_g   = (const float*)d_in[1];
    const float* pe_W       = (const float*)d_in[2];
    const float* pe_b       = (const float*)d_in[3];
    const float* pe_ln2_g   = (const float*)d_in[4];
    const float* attn_ln_g  = (const float*)d_in[5];
    const float* qn_g       = (const float*)d_in[6];
    const float* kn_g       = (const float*)d_in[7];
    const float* Wq         = (const float*)d_in[8];
    const float* Wkv        = (const float*)d_in[9];
    const float* Wo         = (const float*)d_in[10];
    const float* ff_ln_g    = (const float*)d_in[11];
    const float* W1         = (const float*)d_in[12];
    const float* b1         = (const float*)d_in[13];
    const float* W2         = (const float*)d_in[14];
    const float* b2         = (const float*)d_in[15];
    const float* final_ln_g = (const float*)d_in[16];
    const int*   h_idx      = (const int*)d_in[17];
    const int*   w_idx      = (const int*)d_in[18];
    const int*   lengths    = (const int*)d_in[19];

    float *x, *q, *kv;
    __half *xn, *ao, *hb, *wpk;
    cudaGetSymbolAddress((void**)&x,   g_x);
    cudaGetSymbolAddress((void**)&xn,  g_xn);
    cudaGetSymbolAddress((void**)&q,   g_q);
    cudaGetSymbolAddress((void**)&kv,  g_kv);
    cudaGetSymbolAddress((void**)&ao,  g_ao);
    cudaGetSymbolAddress((void**)&hb,  g_h);
    cudaGetSymbolAddress((void**)&wpk, g_wpk);

    cudaFuncSetAttribute(gemm_tc<0>, cudaFuncAttributeMaxDynamicSharedMemorySize, GEMM_SMEM);
    cudaFuncSetAttribute(gemm_tc<1>, cudaFuncAttributeMaxDynamicSharedMemorySize, GEMM_SMEM);
    cudaFuncSetAttribute(gemm_tc<2>, cudaFuncAttributeMaxDynamicSharedMemorySize, GEMM_SMEM);
    cudaFuncSetAttribute(gemm_tc<3>, cudaFuncAttributeMaxDynamicSharedMemorySize, GEMM_SMEM);
    cudaFuncSetAttribute(gemm_tc<4>, cudaFuncAttributeMaxDynamicSharedMemorySize, GEMM_SMEM);
    cudaFuncSetAttribute(attn_tc, cudaFuncAttributeMaxDynamicSharedMemorySize, ATT_SMEM);

    dim3 t256(256);

    // ---- weight offsets inside g_wpk (halves) ------------------------------
    size_t off_pe = 0;
    size_t off_q [Ll], off_kv[Ll], off_o[Ll], off_1[Ll], off_2[Ll];
    {
        size_t cur = (size_t)DIMd * DIMd;
        for (int i = 0; i < Ll; i++) {
            off_q [i] = cur; cur += (size_t)DIMd * DIMd;
            off_kv[i] = cur; cur += (size_t)DIMd * 2 * DIMd;
            off_o [i] = cur; cur += (size_t)DIMd * DIMd;
            off_1 [i] = cur; cur += (size_t)DIMd * MLPm;
            off_2 [i] = cur; cur += (size_t)MLPm * DIMd;
        }
    }

    PackTable tab;
    int ti = 0;
    tab.d[ti++] = { pe_W, wpk + off_pe, DIMd, DIMd };
    for (int i = 0; i < Ll; i++) {
        tab.d[ti++] = { Wq  + (size_t)i * DIMd * DIMd,     wpk + off_q [i], DIMd, DIMd };
        tab.d[ti++] = { Wkv + (size_t)i * DIMd * 2 * DIMd, wpk + off_kv[i], DIMd, 2 * DIMd };
        tab.d[ti++] = { Wo  + (size_t)i * DIMd * DIMd,     wpk + off_o [i], DIMd, DIMd };
        tab.d[ti++] = { W1  + (size_t)i * DIMd * MLPm,     wpk + off_1 [i], DIMd, MLPm };
        tab.d[ti++] = { W2  + (size_t)i * MLPm * DIMd,     wpk + off_2 [i], MLPm, DIMd };
    }
    pack_all<<<dim3(288, 11), t256>>>(tab);

    dim3 gN768(DIMd / 128, Mrows / 128);       // (6, 64)
    dim3 gN1536(2 * DIMd / 128, Mrows / 128);  // (12, 64)
    dim3 gN3072(MLPm / 128, Mrows / 128);      // (24, 64)

    // patch embedding: LN -> Linear+bias -> LN
    ln_k<1><<<Mrows, t256>>>(patches, pe_ln1_g, xn);
    gemm_tc<1><<<gN768, t256, GEMM_SMEM>>>(xn, wpk + off_pe, pe_b, nullptr, x, DIMd, DIMd);
    ln_k<0><<<Mrows, t256>>>(x, pe_ln2_g, x);

    for (int i = 0; i < Ll; i++) {
        ln_k<1><<<Mrows, t256>>>(x, attn_ln_g + (size_t)i * DIMd, xn);
        gemm_tc<0><<<gN768, t256, GEMM_SMEM>>>(xn, wpk + off_q[i], nullptr, nullptr, q, DIMd, DIMd);
        gemm_tc<0><<<gN1536, t256, GEMM_SMEM>>>(xn, wpk + off_kv[i], nullptr, nullptr, kv, DIMd, 2 * DIMd);
        qkrope_k<<<(3 * Mrows * Hh) / 8, t256>>>(
            q, kv, qn_g + (size_t)i * Hh * DHd, kn_g + (size_t)i * Hh * DHd,
            h_idx, w_idx);
        attn_tc<<<dim3(Nn / 128, Hh, Bb), t256, ATT_SMEM>>>(q, kv, lengths, ao);
        gemm_tc<3><<<gN768, t256, GEMM_SMEM>>>(ao, wpk + off_o[i], nullptr, x, x, DIMd, DIMd);
        ln_k<1><<<Mrows, t256>>>(x, ff_ln_g + (size_t)i * DIMd, xn);
        gemm_tc<2><<<gN3072, t256, GEMM_SMEM>>>(xn, wpk + off_1[i], b1 + (size_t)i * MLPm, nullptr, hb, DIMd, MLPm);
        gemm_tc<4><<<gN768, t256, GEMM_SMEM>>>(hb, wpk + off_2[i], b2 + (size_t)i * DIMd, x, x, MLPm, DIMd);
    }

    ln_k<0><<<Mrows, t256>>>(x, final_ln_g, (float*)d_out);

    if (out_size > Mrows * DIMd) {
        mask_k<<<(Bb * Nn + 255) / 256, t256>>>(lengths,
                                                (float*)d_out + (size_t)Mrows * DIMd);
    }
}

// round 9
// speedup vs baseline: 1.8125x; 1.8125x over previous
#include <cuda_runtime.h>
#include <cuda_bf16.h>
#include <cuda_fp16.h>
#include <math.h>
#include <stdint.h>

// Problem dims
#define Bb   4
#define Nn   2048
#define DIMd 768
#define Hh   12
#define DHd  64
#define MLPm 3072
#define Ll   2
#define Mrows (Bb*Nn)   // 8192

// ---------------- scratch (device globals: allocation-free) ----------------
__device__ float  g_x [Mrows*DIMd];
__device__ __half g_xn[Mrows*DIMd];
__device__ __half g_q [Mrows*DIMd];
__device__ __half g_kv[Mrows*2*DIMd];
__device__ __half g_ao[Mrows*DIMd];
__device__ __half g_h [Mrows*MLPm];
#define WPK_LAYER (DIMd*DIMd + DIMd*2*DIMd + DIMd*DIMd + DIMd*MLPm + MLPm*DIMd)
__device__ __half g_wpk[DIMd*DIMd + 2*WPK_LAYER];

// ---------------- PTX helpers ----------------------------------------------
__device__ __forceinline__ unsigned cvta_s(const void* p) {
    return (unsigned)__cvta_generic_to_shared(p);
}
#define CPA16(dst, src) asm volatile("cp.async.cg.shared.global [%0], [%1], 16;" :: "r"(dst), "l"(src))
#define CPCOMMIT()      asm volatile("cp.async.commit_group;")
#define CPWAIT2()       asm volatile("cp.async.wait_group 2;")
#define CPWAIT1()       asm volatile("cp.async.wait_group 1;")
#define CPWAIT0()       asm volatile("cp.async.wait_group 0;")

// fp16 mma m16n8k16
__device__ __forceinline__ void mma16(float& c0, float& c1, float& c2, float& c3,
                                      uint32_t a0, uint32_t a1, uint32_t a2, uint32_t a3,
                                      uint32_t b0, uint32_t b1) {
    asm volatile(
        "mma.sync.aligned.m16n8k16.row.col.f32.f16.f16.f32 "
        "{%0,%1,%2,%3},{%4,%5,%6,%7},{%8,%9},{%0,%1,%2,%3};"
        : "+f"(c0), "+f"(c1), "+f"(c2), "+f"(c3)
        : "r"(a0), "r"(a1), "r"(a2), "r"(a3), "r"(b0), "r"(b1));
}

__device__ __forceinline__ void ldmx4t(uint32_t& r0, uint32_t& r1,
                                       uint32_t& r2, uint32_t& r3, uint32_t addr) {
    asm volatile("ldmatrix.sync.aligned.m8n8.x4.trans.shared.b16 {%0,%1,%2,%3}, [%4];"
                 : "=r"(r0), "=r"(r1), "=r"(r2), "=r"(r3) : "r"(addr));
}

// ---------------- single-launch weight pack (fp16 B-fragment layout) -------
struct PackDesc { const float* src; __half* dst; int K; int Nc; };
struct PackTable { PackDesc d[11]; };

__global__ void __launch_bounds__(256) pack_all(PackTable tab)
{
    __shared__ float Ws[32][257];
    PackDesc pd = tab.d[blockIdx.y];
    int tn = pd.Nc >> 8;
    int total = tn * (pd.K >> 5);
    int bx = blockIdx.x;
    if (bx >= total) return;
    int n0 = (bx % tn) << 8, kb = bx / tn;
    const float* W = pd.src;
    int Nc = pd.Nc;
    int tid = threadIdx.x;
#pragma unroll
    for (int p = 0; p < 8; p++) {
        int idx = tid + p * 256;
        int r = idx >> 6, c4 = (idx & 63) << 2;
        float4 v = *(const float4*)(W + (size_t)(kb * 32 + r) * Nc + n0 + c4);
        Ws[r][c4] = v.x; Ws[r][c4 + 1] = v.y;
        Ws[r][c4 + 2] = v.z; Ws[r][c4 + 3] = v.w;
    }
    __syncthreads();
    __half* out = pd.dst + ((size_t)kb * (Nc >> 3) + (n0 >> 3)) * 256;
#pragma unroll
    for (int p = 0; p < 8; p++) {
        int q = tid + p * 256;        // 2048 chunks of 4 halves
        int lg = q >> 6;
        int w  = q & 63;
        int ks = w >> 5;
        int l  = w & 31;
        int g = l >> 2, t = l & 3;
        int n = lg * 8 + g;
        int kbase = ks * 16;
        __half2 p0 = __floats2half2_rn(Ws[kbase + 2 * t][n], Ws[kbase + 2 * t + 1][n]);
        __half2 p1 = __floats2half2_rn(Ws[kbase + 2 * t + 8][n], Ws[kbase + 2 * t + 9][n]);
        __half* dst = out + ((size_t)lg * 2 + ks) * 128 + l * 4;
        *(__half2*)(dst)     = p0;
        *(__half2*)(dst + 2) = p1;
    }
}

// ---------------- LayerNorm (OH: output half for GEMM A operands) ----------
template<int OH>
__global__ void __launch_bounds__(256) ln_k(const float* __restrict__ X,
                                            const float* __restrict__ g,
                                            void* __restrict__ Yv)
{
    int row = blockIdx.x;
    const float* x = X + (size_t)row * DIMd;
    int tid = threadIdx.x;
    float v[3]; float s = 0.f, sq = 0.f;
#pragma unroll
    for (int i = 0; i < 3; i++) {
        v[i] = x[tid + i * 256];
        s += v[i]; sq += v[i] * v[i];
    }
#pragma unroll
    for (int o = 16; o; o >>= 1) {
        s  += __shfl_xor_sync(~0u, s, o);
        sq += __shfl_xor_sync(~0u, sq, o);
    }
    __shared__ float red[2][8];
    int w = tid >> 5, lane = tid & 31;
    if (lane == 0) { red[0][w] = s; red[1][w] = sq; }
    __syncthreads();
    s = 0.f; sq = 0.f;
#pragma unroll
    for (int j = 0; j < 8; j++) { s += red[0][j]; sq += red[1][j]; }
    float mean = s * (1.f / DIMd);
    float var  = sq * (1.f / DIMd) - mean * mean;
    float rstd = rsqrtf(var + 1e-5f);
#pragma unroll
    for (int i = 0; i < 3; i++) {
        int c = tid + i * 256;
        float o = (v[i] - mean) * rstd * g[c];
        if (OH) ((__half*)Yv)[(size_t)row * DIMd + c] = __float2half_rn(o);
        else    ((float*)Yv)[(size_t)row * DIMd + c] = o;
    }
}

// ---------------- fp16 TC GEMM, tile 128x128, 4-stage cp.async -------------
// 8 warps: 4(m) x 2(n), each 32x64, k-step 32 (2 x k16 mma).
// EPI: 0 half out, 1 +bias(float), 2 gelu(x+b)->half,
//      3 +res(float), 4 +bias+res(float)
#define A_LD 40                       // halves per row
#define A_HALVES (128*A_LD)           // 5120
#define B_HALVES (16*256)             // 4096
#define STG_HALVES (A_HALVES + B_HALVES)   // 9216
#define GEMM_SMEM (4*STG_HALVES*2)    // 73728 B

template<int EPI>
__global__ void __launch_bounds__(256, 2) gemm_tc(const __half* __restrict__ A,
                                                  const __half* __restrict__ Wpk,
                                                  const float* __restrict__ bias,
                                                  const float* __restrict__ res,
                                                  void* __restrict__ Cv,
                                                  int K, int Nc)
{
    extern __shared__ __half smh[];
    uint32_t smem_base = cvta_s(smh);
    int tid = threadIdx.x;
    int warp = tid >> 5, lane = tid & 31;
    int g = lane >> 2, t = lane & 3;
    int wm = (warp >> 1) * 32;
    int warpn = warp & 1;
    int m0 = blockIdx.y * 128, n0 = blockIdx.x * 128;

    const __half* Ag = A + (size_t)m0 * K;
    const __half* Bg = Wpk + (size_t)(n0 >> 3) * 256;
    size_t bstride = (size_t)(Nc >> 3) * 256;   // halves per k-block

    float acc[2][8][4];
#pragma unroll
    for (int a = 0; a < 2; a++)
#pragma unroll
        for (int b = 0; b < 8; b++)
#pragma unroll
            for (int c = 0; c < 4; c++) acc[a][b][c] = 0.f;

    auto loadA = [&](int s, int kb) {
        uint32_t dst = smem_base + (uint32_t)(s * STG_HALVES) * 2;
#pragma unroll
        for (int p = 0; p < 2; p++) {
            int q = tid + p * 256;
            int m = q >> 2, j = q & 3;
            CPA16(dst + (uint32_t)m * (A_LD * 2) + (uint32_t)j * 16,
                  Ag + (size_t)m * K + kb * 32 + j * 8);
        }
    };
    auto loadB = [&](int s, int kb) {
        uint32_t dst = smem_base + (uint32_t)(s * STG_HALVES + A_HALVES) * 2;
        const __half* src = Bg + (size_t)kb * bstride;
#pragma unroll
        for (int p = 0; p < 2; p++) {
            int q = tid + p * 256;
            CPA16(dst + (uint32_t)q * 16, src + (size_t)q * 8);
        }
    };

    int niter = K >> 5;
    loadA(0, 0); loadB(0, 0); CPCOMMIT();
    loadA(1, 1); loadB(1, 1); CPCOMMIT();
    loadA(2, 2); loadB(2, 2); CPCOMMIT();

    for (int it = 0; it < niter; it++) {
        if (it + 3 <= niter)      { CPWAIT2(); }
        else if (it + 2 <= niter) { CPWAIT1(); }
        else                      { CPWAIT0(); }
        __syncthreads();
        if (it + 3 < niter) {
            loadA((it + 3) & 3, it + 3);
            loadB((it + 3) & 3, it + 3);
            CPCOMMIT();
        }
        const __half* As = smh + (it & 3) * STG_HALVES;
        const __half* Bs = As + A_HALVES;

#pragma unroll
        for (int ks = 0; ks < 2; ks++) {
            uint32_t af[2][4], bf[8][2];
#pragma unroll
            for (int mt = 0; mt < 2; mt++) {
                int r = wm + mt * 16 + g;
                af[mt][0] = *(const uint32_t*)&As[r * A_LD + ks * 16 + 2 * t];
                af[mt][1] = *(const uint32_t*)&As[(r + 8) * A_LD + ks * 16 + 2 * t];
                af[mt][2] = *(const uint32_t*)&As[r * A_LD + ks * 16 + 2 * t + 8];
                af[mt][3] = *(const uint32_t*)&As[(r + 8) * A_LD + ks * 16 + 2 * t + 8];
            }
#pragma unroll
            for (int nt = 0; nt < 8; nt++) {
                uint2 bb = *(const uint2*)&Bs[(((warpn * 8 + nt) * 2 + ks) << 7) + lane * 4];
                bf[nt][0] = bb.x; bf[nt][1] = bb.y;
            }
#pragma unroll
            for (int mt = 0; mt < 2; mt++)
#pragma unroll
                for (int nt = 0; nt < 8; nt++)
                    mma16(acc[mt][nt][0], acc[mt][nt][1],
                          acc[mt][nt][2], acc[mt][nt][3],
                          af[mt][0], af[mt][1], af[mt][2], af[mt][3],
                          bf[nt][0], bf[nt][1]);
        }
        __syncthreads();
    }

    int wn = warpn * 64;
    float* C = (float*)Cv;
    __half* Ch = (__half*)Cv;
#pragma unroll
    for (int mt = 0; mt < 2; mt++) {
        int row = m0 + wm + mt * 16 + g;
#pragma unroll
        for (int nt = 0; nt < 8; nt++) {
            int col = n0 + wn + nt * 8 + 2 * t;
            float v0 = acc[mt][nt][0], v1 = acc[mt][nt][1];
            float v2 = acc[mt][nt][2], v3 = acc[mt][nt][3];
            if (EPI == 1 || EPI == 2 || EPI == 4) {
                float b0 = bias[col], b1 = bias[col + 1];
                v0 += b0; v1 += b1; v2 += b0; v3 += b1;
            }
            size_t o0 = (size_t)row * Nc + col;
            size_t o1 = (size_t)(row + 8) * Nc + col;
            if (EPI == 2) {
                v0 = 0.5f * v0 * (1.0f + erff(v0 * 0.70710678118654752f));
                v1 = 0.5f * v1 * (1.0f + erff(v1 * 0.70710678118654752f));
                v2 = 0.5f * v2 * (1.0f + erff(v2 * 0.70710678118654752f));
                v3 = 0.5f * v3 * (1.0f + erff(v3 * 0.70710678118654752f));
            }
            if (EPI == 0 || EPI == 2) {
                *(__half2*)&Ch[o0] = __floats2half2_rn(v0, v1);
                *(__half2*)&Ch[o1] = __floats2half2_rn(v2, v3);
            } else {
                if (EPI == 3 || EPI == 4) {
                    float2 r0 = *(const float2*)(res + o0);
                    float2 r1 = *(const float2*)(res + o1);
                    v0 += r0.x; v1 += r0.y; v2 += r1.x; v3 += r1.y;
                }
                *(float2*)(C + o0) = make_float2(v0, v1);
                *(float2*)(C + o1) = make_float2(v2, v3);
            }
        }
    }
}

// -------- QK RMSNorm + 2D RoPE on half q/kv ---------------------------------
__global__ void __launch_bounds__(256) qkrope_k(__half* __restrict__ Q,
                                                __half* __restrict__ KV,
                                                const float* __restrict__ qg,
                                                const float* __restrict__ kg,
                                                const int* __restrict__ h_idx,
                                                const int* __restrict__ w_idx)
{
    int warp = blockIdx.x * 8 + (threadIdx.x >> 5);
    int lane = threadIdx.x & 31;
    int grp = warp / (Mrows * Hh);       // 0=Q, 1=K
    int rid = warp - grp * (Mrows * Hh);
    int bn = rid / Hh;
    int h  = rid % Hh;

    __half* ptr;
    const float* g;
    if (grp == 0) { ptr = Q  + (size_t)bn * DIMd     + h * DHd; g = qg + h * DHd; }
    else          { ptr = KV + (size_t)bn * 2 * DIMd + h * DHd; g = kg + h * DHd; }

    float v1 = __half2float(ptr[lane]);
    float v2 = __half2float(ptr[lane + 32]);
    float ss = v1 * v1 + v2 * v2;
#pragma unroll
    for (int o = 16; o; o >>= 1) ss += __shfl_xor_sync(~0u, ss, o);
    float sc = 8.0f / fmaxf(sqrtf(ss), 1e-12f);
    v1 = v1 * sc * g[lane];
    v2 = v2 * sc * g[lane + 32];

    int f = lane & 15;
    float invf = exp2f(-(float)f * (13.287712379549449f / 16.0f));
    float th1 = (float)h_idx[bn] * invf;
    float th2 = (float)w_idx[bn] * invf;
    float p1 = __shfl_xor_sync(~0u, v1, 16);
    float p2 = __shfl_xor_sync(~0u, v2, 16);
    float rh1 = (lane < 16) ? -p1 : p1;
    float rh2 = (lane < 16) ? -p2 : p2;
    ptr[lane]      = __float2half_rn(v1 * cosf(th1) + rh1 * sinf(th1));
    ptr[lane + 32] = __float2half_rn(v2 * cosf(th2) + rh2 * sinf(th2));
}

// ---------------- fp16 TC flash attention ----------------------------------
// 256 threads = 8 warps x 16 q-rows, 64-key tiles, Q frags in registers,
// cp.async double-buffered K/V (half), ldmatrix.trans for V fragments.
#define KS_LDH 72   // halves per row (144B)
#define VS_LDH 72
#define PS_LDH 72
#define ATT_SMEM ((2*64*KS_LDH + 2*64*VS_LDH + 128*PS_LDH) * 2)   // 55296

__global__ void __launch_bounds__(256, 2) attn_tc(const __half* __restrict__ Q,
                                                  const __half* __restrict__ KV,
                                                  const int* __restrict__ lengths,
                                                  __half* __restrict__ O)
{
    extern __shared__ __half smh[];
    __half* KsB = smh;                        // 2 x [64][KS_LDH]
    __half* VsB = KsB + 2 * 64 * KS_LDH;      // 2 x [64][VS_LDH]
    __half* Ps  = VsB + 2 * 64 * VS_LDH;      // [128][PS_LDH]
    uint32_t vs_base = cvta_s(VsB);

    int b = blockIdx.z, h = blockIdx.y, q0 = blockIdx.x * 128;
    int tid = threadIdx.x;
    int warp = tid >> 5, lane = tid & 31;
    int g = lane >> 2, t = lane & 3;
    int wq = warp * 16;

    const __half* Qg = Q  + ((size_t)b * Nn + q0) * DIMd + h * DHd;
    const __half* Kg = KV + ((size_t)b * Nn) * 2 * DIMd + h * DHd;
    int len = lengths[b];

    // Q fragments in registers
    uint32_t qf[4][4];
    {
        const __half* r0 = Qg + (size_t)(wq + g) * DIMd;
        const __half* r1 = r0 + 8 * DIMd;
#pragma unroll
        for (int ks = 0; ks < 4; ks++) {
            qf[ks][0] = *(const uint32_t*)&r0[ks * 16 + 2 * t];
            qf[ks][1] = *(const uint32_t*)&r1[ks * 16 + 2 * t];
            qf[ks][2] = *(const uint32_t*)&r0[ks * 16 + 2 * t + 8];
            qf[ks][3] = *(const uint32_t*)&r1[ks * 16 + 2 * t + 8];
        }
    }

    float Oa[8][4];
    float mrow[2], lrow[2];
#pragma unroll
    for (int n = 0; n < 8; n++)
#pragma unroll
        for (int c = 0; c < 4; c++) Oa[n][c] = 0.f;
    mrow[0] = mrow[1] = -1e30f;
    lrow[0] = lrow[1] = 0.f;

    int ntiles = (len + 63) >> 6;

    auto loadKV = [&](int buf, int kt) {
        uint32_t Kd = cvta_s(KsB) + (uint32_t)buf * (64 * KS_LDH * 2);
        uint32_t Vd = vs_base + (uint32_t)buf * (64 * VS_LDH * 2);
#pragma unroll
        for (int p = 0; p < 2; p++) {
            int idx = tid + p * 256;      // 512 chunks of 8 halves
            int r = idx >> 3, c8 = (idx & 7) << 3;
            const __half* kp = Kg + (size_t)(kt * 64 + r) * (2 * DIMd) + c8;
            CPA16(Kd + (uint32_t)r * (KS_LDH * 2) + (uint32_t)c8 * 2, kp);
            CPA16(Vd + (uint32_t)r * (VS_LDH * 2) + (uint32_t)c8 * 2, kp + DIMd);
        }
    };

    loadKV(0, 0); CPCOMMIT();

    for (int kt = 0; kt < ntiles; kt++) {
        CPWAIT0();
        __syncthreads();
        if (kt + 1 < ntiles) { loadKV((kt + 1) & 1, kt + 1); CPCOMMIT(); }
        const __half* Ks = KsB + (kt & 1) * 64 * KS_LDH;
        uint32_t Vsb = vs_base + (uint32_t)(kt & 1) * (64 * VS_LDH * 2);

        // S = Q K^T  (B-frags straight from K rows: k-contiguous)
        float S[8][4];
#pragma unroll
        for (int n = 0; n < 8; n++)
#pragma unroll
            for (int c = 0; c < 4; c++) S[n][c] = 0.f;

#pragma unroll
        for (int ks = 0; ks < 4; ks++) {
#pragma unroll
            for (int nt = 0; nt < 8; nt++) {
                int key = nt * 8 + g;
                uint32_t b0 = *(const uint32_t*)&Ks[key * KS_LDH + ks * 16 + 2 * t];
                uint32_t b1 = *(const uint32_t*)&Ks[key * KS_LDH + ks * 16 + 2 * t + 8];
                mma16(S[nt][0], S[nt][1], S[nt][2], S[nt][3],
                      qf[ks][0], qf[ks][1], qf[ks][2], qf[ks][3], b0, b1);
            }
        }

        // key mask
#pragma unroll
        for (int nt = 0; nt < 8; nt++) {
            int kc = kt * 64 + nt * 8 + 2 * t;
            if (kc >= len)     { S[nt][0] = -1e30f; S[nt][2] = -1e30f; }
            if (kc + 1 >= len) { S[nt][1] = -1e30f; S[nt][3] = -1e30f; }
        }

        // online softmax
#pragma unroll
        for (int half = 0; half < 2; half++) {
            int i0 = half * 2, i1 = half * 2 + 1;
            float rm = -1e30f;
#pragma unroll
            for (int nt = 0; nt < 8; nt++)
                rm = fmaxf(rm, fmaxf(S[nt][i0], S[nt][i1]));
            rm = fmaxf(rm, __shfl_xor_sync(~0u, rm, 1));
            rm = fmaxf(rm, __shfl_xor_sync(~0u, rm, 2));
            float mn = fmaxf(mrow[half], rm);
            float rs = 0.f;
#pragma unroll
            for (int nt = 0; nt < 8; nt++) {
                S[nt][i0] = __expf(S[nt][i0] - mn);
                S[nt][i1] = __expf(S[nt][i1] - mn);
                rs += S[nt][i0] + S[nt][i1];
            }
            rs += __shfl_xor_sync(~0u, rs, 1);
            rs += __shfl_xor_sync(~0u, rs, 2);
            float corr = __expf(mrow[half] - mn);
            lrow[half] = lrow[half] * corr + rs;
            mrow[half] = mn;
#pragma unroll
            for (int nt = 0; nt < 8; nt++) {
                Oa[nt][i0] *= corr;
                Oa[nt][i1] *= corr;
            }
        }

        // stage P as half (warp-private rows)
        {
            int r = wq + g;
#pragma unroll
            for (int nt = 0; nt < 8; nt++) {
                *(__half2*)&Ps[r * PS_LDH + nt * 8 + 2 * t] =
                    __floats2half2_rn(S[nt][0], S[nt][1]);
                *(__half2*)&Ps[(r + 8) * PS_LDH + nt * 8 + 2 * t] =
                    __floats2half2_rn(S[nt][2], S[nt][3]);
            }
        }
        __syncwarp();

        // O += P V  (V B-frags via ldmatrix.x4.trans)
#pragma unroll
        for (int ks = 0; ks < 4; ks++) {
            uint32_t a0 = *(const uint32_t*)&Ps[(wq + g) * PS_LDH + ks * 16 + 2 * t];
            uint32_t a1 = *(const uint32_t*)&Ps[(wq + 8 + g) * PS_LDH + ks * 16 + 2 * t];
            uint32_t a2 = *(const uint32_t*)&Ps[(wq + g) * PS_LDH + ks * 16 + 2 * t + 8];
            uint32_t a3 = *(const uint32_t*)&Ps[(wq + 8 + g) * PS_LDH + ks * 16 + 2 * t + 8];
#pragma unroll
            for (int np = 0; np < 4; np++) {
                int vrow = ks * 16 + (lane & 15);
                int vcol = np * 16 + ((lane >> 4) << 3);
                uint32_t addr = Vsb + (uint32_t)vrow * (VS_LDH * 2) + (uint32_t)vcol * 2;
                uint32_t b00, b01, b10, b11;
                ldmx4t(b00, b01, b10, b11, addr);
                mma16(Oa[np * 2][0], Oa[np * 2][1], Oa[np * 2][2], Oa[np * 2][3],
                      a0, a1, a2, a3, b00, b01);
                mma16(Oa[np * 2 + 1][0], Oa[np * 2 + 1][1], Oa[np * 2 + 1][2], Oa[np * 2 + 1][3],
                      a0, a1, a2, a3, b10, b11);
            }
        }
    }

    // write out (ao is only ever a GEMM A operand -> half)
    {
        int row0 = q0 + wq + g;
        float inv0 = 1.0f / lrow[0];
        float inv1 = 1.0f / lrow[1];
#pragma unroll
        for (int nt = 0; nt < 8; nt++) {
            int col = h * DHd + nt * 8 + 2 * t;
            size_t o0 = ((size_t)b * Nn + row0) * DIMd + col;
            size_t o1 = ((size_t)b * Nn + row0 + 8) * DIMd + col;
            *(__half2*)&O[o0] = __floats2half2_rn(Oa[nt][0] * inv0, Oa[nt][1] * inv0);
            *(__half2*)&O[o1] = __floats2half2_rn(Oa[nt][2] * inv1, Oa[nt][3] * inv1);
        }
    }
}

// ---------------- mask tail writer -----------------------------------------
__global__ void mask_k(const int* __restrict__ lengths, float* __restrict__ out)
{
    int i = blockIdx.x * blockDim.x + threadIdx.x;
    if (i < Bb * Nn) {
        int b = i / Nn, n = i % Nn;
        out[i] = (n < lengths[b]) ? 1.0f : 0.0f;
    }
}

// ---------------- host orchestration ---------------------------------------
extern "C" void kernel_launch(void* const* d_in, const int* in_sizes, int n_in,
                              void* d_out, int out_size)
{
    const float* patches    = (const float*)d_in[0];
    const float* pe_ln1_g   = (const float*)d_in[1];
    const float* pe_W       = (const float*)d_in[2];
    const float* pe_b       = (const float*)d_in[3];
    const float* pe_ln2_g   = (const float*)d_in[4];
    const float* attn_ln_g  = (const float*)d_in[5];
    const float* qn_g       = (const float*)d_in[6];
    const float* kn_g       = (const float*)d_in[7];
    const float* Wq         = (const float*)d_in[8];
    const float* Wkv        = (const float*)d_in[9];
    const float* Wo         = (const float*)d_in[10];
    const float* ff_ln_g    = (const float*)d_in[11];
    const float* W1         = (const float*)d_in[12];
    const float* b1         = (const float*)d_in[13];
    const float* W2         = (const float*)d_in[14];
    const float* b2         = (const float*)d_in[15];
    const float* final_ln_g = (const float*)d_in[16];
    const int*   h_idx      = (const int*)d_in[17];
    const int*   w_idx      = (const int*)d_in[18];
    const int*   lengths    = (const int*)d_in[19];

    float *x;
    __half *xn, *q, *kv, *ao, *hb, *wpk;
    cudaGetSymbolAddress((void**)&x,   g_x);
    cudaGetSymbolAddress((void**)&xn,  g_xn);
    cudaGetSymbolAddress((void**)&q,   g_q);
    cudaGetSymbolAddress((void**)&kv,  g_kv);
    cudaGetSymbolAddress((void**)&ao,  g_ao);
    cudaGetSymbolAddress((void**)&hb,  g_h);
    cudaGetSymbolAddress((void**)&wpk, g_wpk);

    cudaFuncSetAttribute(gemm_tc<0>, cudaFuncAttributeMaxDynamicSharedMemorySize, GEMM_SMEM);
    cudaFuncSetAttribute(gemm_tc<1>, cudaFuncAttributeMaxDynamicSharedMemorySize, GEMM_SMEM);
    cudaFuncSetAttribute(gemm_tc<2>, cudaFuncAttributeMaxDynamicSharedMemorySize, GEMM_SMEM);
    cudaFuncSetAttribute(gemm_tc<3>, cudaFuncAttributeMaxDynamicSharedMemorySize, GEMM_SMEM);
    cudaFuncSetAttribute(gemm_tc<4>, cudaFuncAttributeMaxDynamicSharedMemorySize, GEMM_SMEM);
    cudaFuncSetAttribute(attn_tc, cudaFuncAttributeMaxDynamicSharedMemorySize, ATT_SMEM);

    dim3 t256(256);

    // ---- weight offsets inside g_wpk (halves) ------------------------------
    size_t off_pe = 0;
    size_t off_q [Ll], off_kv[Ll], off_o[Ll], off_1[Ll], off_2[Ll];
    {
        size_t cur = (size_t)DIMd * DIMd;
        for (int i = 0; i < Ll; i++) {
            off_q [i] = cur; cur += (size_t)DIMd * DIMd;
            off_kv[i] = cur; cur += (size_t)DIMd * 2 * DIMd;
            off_o [i] = cur; cur += (size_t)DIMd * DIMd;
            off_1 [i] = cur; cur += (size_t)DIMd * MLPm;
            off_2 [i] = cur; cur += (size_t)MLPm * DIMd;
        }
    }

    PackTable tab;
    int ti = 0;
    tab.d[ti++] = { pe_W, wpk + off_pe, DIMd, DIMd };
    for (int i = 0; i < Ll; i++) {
        tab.d[ti++] = { Wq  + (size_t)i * DIMd * DIMd,     wpk + off_q [i], DIMd, DIMd };
        tab.d[ti++] = { Wkv + (size_t)i * DIMd * 2 * DIMd, wpk + off_kv[i], DIMd, 2 * DIMd };
        tab.d[ti++] = { Wo  + (size_t)i * DIMd * DIMd,     wpk + off_o [i], DIMd, DIMd };
        tab.d[ti++] = { W1  + (size_t)i * DIMd * MLPm,     wpk + off_1 [i], DIMd, MLPm };
        tab.d[ti++] = { W2  + (size_t)i * MLPm * DIMd,     wpk + off_2 [i], MLPm, DIMd };
    }
    pack_all<<<dim3(288, 11), t256>>>(tab);

    dim3 gN768(DIMd / 128, Mrows / 128);       // (6, 64)
    dim3 gN1536(2 * DIMd / 128, Mrows / 128);  // (12, 64)
    dim3 gN3072(MLPm / 128, Mrows / 128);      // (24, 64)

    // patch embedding: LN -> Linear+bias -> LN
    ln_k<1><<<Mrows, t256>>>(patches, pe_ln1_g, xn);
    gemm_tc<1><<<gN768, t256, GEMM_SMEM>>>(xn, wpk + off_pe, pe_b, nullptr, x, DIMd, DIMd);
    ln_k<0><<<Mrows, t256>>>(x, pe_ln2_g, x);

    for (int i = 0; i < Ll; i++) {
        ln_k<1><<<Mrows, t256>>>(x, attn_ln_g + (size_t)i * DIMd, xn);
        gemm_tc<0><<<gN768, t256, GEMM_SMEM>>>(xn, wpk + off_q[i], nullptr, nullptr, q, DIMd, DIMd);
        gemm_tc<0><<<gN1536, t256, GEMM_SMEM>>>(xn, wpk + off_kv[i], nullptr, nullptr, kv, DIMd, 2 * DIMd);
        qkrope_k<<<(2 * Mrows * Hh) / 8, t256>>>(
            q, kv, qn_g + (size_t)i * Hh * DHd, kn_g + (size_t)i * Hh * DHd,
            h_idx, w_idx);
        attn_tc<<<dim3(Nn / 128, Hh, Bb), t256, ATT_SMEM>>>(q, kv, lengths, ao);
        gemm_tc<3><<<gN768, t256, GEMM_SMEM>>>(ao, wpk + off_o[i], nullptr, x, x, DIMd, DIMd);
        ln_k<1><<<Mrows, t256>>>(x, ff_ln_g + (size_t)i * DIMd, xn);
        gemm_tc<2><<<gN3072, t256, GEMM_SMEM>>>(xn, wpk + off_1[i], b1 + (size_t)i * MLPm, nullptr, hb, DIMd, MLPm);
        gemm_tc<4><<<gN768, t256, GEMM_SMEM>>>(hb, wpk + off_2[i], b2 + (size_t)i * DIMd, x, x, MLPm, DIMd);
    }

    ln_k<0><<<Mrows, t256>>>(x, final_ln_g, (float*)d_out);

    if (out_size > Mrows * DIMd) {
        mask_k<<<(Bb * Nn + 255) / 256, t256>>>(lengths,
                                                (float*)d_out + (size_t)Mrows * DIMd);
    }
}

// round 13
// speedup vs baseline: 2.0119x; 1.1100x over previous
#include <cuda_runtime.h>
#include <cuda_bf16.h>
#include <cuda_fp16.h>
#include <math.h>
#include <stdint.h>

// Problem dims
#define Bb   4
#define Nn   2048
#define DIMd 768
#define Hh   12
#define DHd  64
#define MLPm 3072
#define Ll   2
#define Mrows (Bb*Nn)   // 8192

// ---------------- scratch (device globals: allocation-free) ----------------
__device__ float  g_x  [Mrows*DIMd];
__device__ __half g_xn [Mrows*DIMd];
__device__ __half g_qkv[Mrows*3*DIMd];   // per row: [q(768) | k(768) | v(768)]
__device__ __half g_ao [Mrows*DIMd];
__device__ __half g_h  [Mrows*MLPm];
#define WPK_LAYER (DIMd*3*DIMd + DIMd*DIMd + DIMd*MLPm + MLPm*DIMd)
__device__ __half g_wpk[DIMd*DIMd + 2*WPK_LAYER];

// ---------------- PTX helpers ----------------------------------------------
__device__ __forceinline__ unsigned cvta_s(const void* p) {
    return (unsigned)__cvta_generic_to_shared(p);
}
#define CPA16(dst, src) asm volatile("cp.async.cg.shared.global [%0], [%1], 16;" :: "r"(dst), "l"(src))
#define CPCOMMIT()      asm volatile("cp.async.commit_group;")
#define CPWAIT2()       asm volatile("cp.async.wait_group 2;")
#define CPWAIT1()       asm volatile("cp.async.wait_group 1;")
#define CPWAIT0()       asm volatile("cp.async.wait_group 0;")

// fp16 mma m16n8k16
__device__ __forceinline__ void mma16(float& c0, float& c1, float& c2, float& c3,
                                      uint32_t a0, uint32_t a1, uint32_t a2, uint32_t a3,
                                      uint32_t b0, uint32_t b1) {
    asm volatile(
        "mma.sync.aligned.m16n8k16.row.col.f32.f16.f16.f32 "
        "{%0,%1,%2,%3},{%4,%5,%6,%7},{%8,%9},{%0,%1,%2,%3};"
        : "+f"(c0), "+f"(c1), "+f"(c2), "+f"(c3)
        : "r"(a0), "r"(a1), "r"(a2), "r"(a3), "r"(b0), "r"(b1));
}

__device__ __forceinline__ void ldmx4(uint32_t* r, uint32_t addr) {
    asm volatile("ldmatrix.sync.aligned.m8n8.x4.shared.b16 {%0,%1,%2,%3}, [%4];"
                 : "=r"(r[0]), "=r"(r[1]), "=r"(r[2]), "=r"(r[3]) : "r"(addr));
}
__device__ __forceinline__ void ldmx4t(uint32_t& r0, uint32_t& r1,
                                       uint32_t& r2, uint32_t& r3, uint32_t addr) {
    asm volatile("ldmatrix.sync.aligned.m8n8.x4.trans.shared.b16 {%0,%1,%2,%3}, [%4];"
                 : "=r"(r0), "=r"(r1), "=r"(r2), "=r"(r3) : "r"(addr));
}

// ---------------- single-launch weight pack (fp16 B-fragment layout) -------
// Per (kb, 8-col group lg): 256 halves; lane l owns halves [l*8 .. l*8+7]:
//   ks0: {W[kb*32+2t][n], W[..+2t+1][n], W[..2t+8][n], W[..2t+9][n]}
//   ks1: same with k base +16.     (l = 4g+t, n = lg*8+g)
struct PackDesc { const float* src; __half* dst; int K; int Nc; int dstNc; int n0off; };
struct PackTable { PackDesc d[11]; };

__global__ void __launch_bounds__(256) pack_all(PackTable tab)
{
    __shared__ float Ws[32][257];
    PackDesc pd = tab.d[blockIdx.y];
    int tn = pd.Nc >> 8;
    int total = tn * (pd.K >> 5);
    int bx = blockIdx.x;
    if (bx >= total) return;
    int n0 = (bx % tn) << 8, kb = bx / tn;
    const float* W = pd.src;
    int Nc = pd.Nc;
    int tid = threadIdx.x;
#pragma unroll
    for (int p = 0; p < 8; p++) {
        int idx = tid + p * 256;
        int r = idx >> 6, c4 = (idx & 63) << 2;
        float4 v = *(const float4*)(W + (size_t)(kb * 32 + r) * Nc + n0 + c4);
        Ws[r][c4] = v.x; Ws[r][c4 + 1] = v.y;
        Ws[r][c4 + 2] = v.z; Ws[r][c4 + 3] = v.w;
    }
    __syncthreads();
    __half* out = pd.dst + ((size_t)kb * (pd.dstNc >> 3) + ((n0 + pd.n0off) >> 3)) * 256;
#pragma unroll
    for (int p = 0; p < 8; p++) {
        int q = tid + p * 256;        // 2048 chunks of 4 halves
        int lg = q >> 6;
        int w  = q & 63;
        int ks = w >> 5;
        int l  = w & 31;
        int g = l >> 2, t = l & 3;
        int n = lg * 8 + g;
        int kbase = ks * 16;
        __half2 p0 = __floats2half2_rn(Ws[kbase + 2 * t][n], Ws[kbase + 2 * t + 1][n]);
        __half2 p1 = __floats2half2_rn(Ws[kbase + 2 * t + 8][n], Ws[kbase + 2 * t + 9][n]);
        __half* dst = out + (size_t)lg * 256 + l * 8 + ks * 4;
        *(__half2*)(dst)     = p0;
        *(__half2*)(dst + 2) = p1;
    }
}

// ---------------- LayerNorm: warp per row (no smem, no block sync) ---------
template<int OH>
__global__ void __launch_bounds__(256) ln_w(const float* __restrict__ X,
                                            const float* __restrict__ g,
                                            void* __restrict__ Yv)
{
    int row  = blockIdx.x * 8 + (threadIdx.x >> 5);
    int lane = threadIdx.x & 31;
    const float* x = X + (size_t)row * DIMd;
    float4 v[6];
    float s = 0.f, sq = 0.f;
#pragma unroll
    for (int j = 0; j < 6; j++) {
        v[j] = *(const float4*)(x + lane * 4 + j * 128);
        s  += v[j].x + v[j].y + v[j].z + v[j].w;
        sq += v[j].x * v[j].x + v[j].y * v[j].y + v[j].z * v[j].z + v[j].w * v[j].w;
    }
#pragma unroll
    for (int o = 16; o; o >>= 1) {
        s  += __shfl_xor_sync(~0u, s, o);
        sq += __shfl_xor_sync(~0u, sq, o);
    }
    float mean = s * (1.f / DIMd);
    float var  = sq * (1.f / DIMd) - mean * mean;
    float rstd = rsqrtf(var + 1e-5f);
#pragma unroll
    for (int j = 0; j < 6; j++) {
        int c = lane * 4 + j * 128;
        float4 gg = *(const float4*)(g + c);
        float o0 = (v[j].x - mean) * rstd * gg.x;
        float o1 = (v[j].y - mean) * rstd * gg.y;
        float o2 = (v[j].z - mean) * rstd * gg.z;
        float o3 = (v[j].w - mean) * rstd * gg.w;
        if (OH) {
            __half* y = (__half*)Yv + (size_t)row * DIMd + c;
            *(__half2*)(y)     = __floats2half2_rn(o0, o1);
            *(__half2*)(y + 2) = __floats2half2_rn(o2, o3);
        } else {
            *(float4*)((float*)Yv + (size_t)row * DIMd + c) = make_float4(o0, o1, o2, o3);
        }
    }
}

// ---------------- fp16 TC GEMM, tile 128x128, 4-stage cp.async -------------
// 8 warps: 4(m) x 2(n), each 32x64, k-step 32 (2 x k16 mma).
// A frags via ldmatrix.x4, B frags via one LDS.128 per (nt).
// EPI: 0 half out, 1 +bias(float), 2 gelu(x+b)->half, 3 +res(float), 4 +bias+res(float)
#define A_LD 40                       // halves per row
#define A_HALVES (128*A_LD)           // 5120
#define B_HALVES (16*256)             // 4096
#define STG_HALVES (A_HALVES + B_HALVES)   // 9216
#define STG_B (STG_HALVES*2)
#define GEMM_SMEM (4*STG_B)           // 73728 B

template<int EPI>
__global__ void __launch_bounds__(256, 2) gemm_tc(const __half* __restrict__ A,
                                                  const __half* __restrict__ Wpk,
                                                  const float* __restrict__ bias,
                                                  const float* __restrict__ res,
                                                  void* __restrict__ Cv,
                                                  int K, int Nc)
{
    extern __shared__ __half smh[];
    uint32_t smem_base = cvta_s(smh);
    int tid = threadIdx.x;
    int warp = tid >> 5, lane = tid & 31;
    int g = lane >> 2, t = lane & 3;
    int wm = (warp >> 1) * 32;
    int warpn = warp & 1;
    int m0 = blockIdx.y * 128, n0 = blockIdx.x * 128;

    const __half* Ag = A + (size_t)m0 * K;
    const __half* Bg = Wpk + (size_t)(n0 >> 3) * 256;
    size_t bstride = (size_t)(Nc >> 3) * 256;   // halves per k-block

    // A ldmatrix addresses (offsets within a stage)
    int quad = lane >> 3, rw = lane & 7;
    uint32_t aoff[2][2];
#pragma unroll
    for (int mt = 0; mt < 2; mt++)
#pragma unroll
        for (int ks = 0; ks < 2; ks++)
            aoff[mt][ks] = (uint32_t)(((wm + mt * 16 + ((quad & 1) << 3) + rw) * A_LD
                                       + ks * 16 + ((quad >> 1) << 3)) * 2);

    float acc[2][8][4];
#pragma unroll
    for (int a = 0; a < 2; a++)
#pragma unroll
        for (int b = 0; b < 8; b++)
#pragma unroll
            for (int c = 0; c < 4; c++) acc[a][b][c] = 0.f;

    auto loadA = [&](int s, int kb) {
        uint32_t dst = smem_base + (uint32_t)s * STG_B;
#pragma unroll
        for (int p = 0; p < 2; p++) {
            int q = tid + p * 256;
            int m = q >> 2, j = q & 3;
            CPA16(dst + (uint32_t)m * (A_LD * 2) + (uint32_t)j * 16,
                  Ag + (size_t)m * K + kb * 32 + j * 8);
        }
    };
    auto loadB = [&](int s, int kb) {
        uint32_t dst = smem_base + (uint32_t)s * STG_B + A_HALVES * 2;
        const __half* src = Bg + (size_t)kb * bstride;
#pragma unroll
        for (int p = 0; p < 2; p++) {
            int q = tid + p * 256;
            CPA16(dst + (uint32_t)q * 16, src + (size_t)q * 8);
        }
    };

    int niter = K >> 5;
    loadA(0, 0); loadB(0, 0); CPCOMMIT();
    loadA(1, 1); loadB(1, 1); CPCOMMIT();
    loadA(2, 2); loadB(2, 2); CPCOMMIT();

    for (int it = 0; it < niter; it++) {
        if (it + 3 <= niter)      { CPWAIT2(); }
        else if (it + 2 <= niter) { CPWAIT1(); }
        else                      { CPWAIT0(); }
        __syncthreads();
        if (it + 3 < niter) {
            loadA((it + 3) & 3, it + 3);
            loadB((it + 3) & 3, it + 3);
            CPCOMMIT();
        }
        uint32_t abase = smem_base + (uint32_t)(it & 3) * STG_B;
        const __half* Bs = smh + (it & 3) * STG_HALVES + A_HALVES + warpn * 8 * 256;

        uint4 bfr[8];
#pragma unroll
        for (int nt = 0; nt < 8; nt++)
            bfr[nt] = *(const uint4*)&Bs[nt * 256 + lane * 8];

#pragma unroll
        for (int ks = 0; ks < 2; ks++) {
            uint32_t af0[4], af1[4];
            ldmx4(af0, abase + aoff[0][ks]);
            ldmx4(af1, abase + aoff[1][ks]);
#pragma unroll
            for (int nt = 0; nt < 8; nt++) {
                uint32_t b0 = ks ? bfr[nt].z : bfr[nt].x;
                uint32_t b1 = ks ? bfr[nt].w : bfr[nt].y;
                mma16(acc[0][nt][0], acc[0][nt][1], acc[0][nt][2], acc[0][nt][3],
                      af0[0], af0[1], af0[2], af0[3], b0, b1);
                mma16(acc[1][nt][0], acc[1][nt][1], acc[1][nt][2], acc[1][nt][3],
                      af1[0], af1[1], af1[2], af1[3], b0, b1);
            }
        }
        __syncthreads();
    }

    int wn = warpn * 64;
    float* C = (float*)Cv;
    __half* Ch = (__half*)Cv;
#pragma unroll
    for (int mt = 0; mt < 2; mt++) {
        int row = m0 + wm + mt * 16 + g;
#pragma unroll
        for (int nt = 0; nt < 8; nt++) {
            int col = n0 + wn + nt * 8 + 2 * t;
            float v0 = acc[mt][nt][0], v1 = acc[mt][nt][1];
            float v2 = acc[mt][nt][2], v3 = acc[mt][nt][3];
            if (EPI == 1 || EPI == 2 || EPI == 4) {
                float b0 = bias[col], b1 = bias[col + 1];
                v0 += b0; v1 += b1; v2 += b0; v3 += b1;
            }
            size_t o0 = (size_t)row * Nc + col;
            size_t o1 = (size_t)(row + 8) * Nc + col;
            if (EPI == 2) {
                v0 = 0.5f * v0 * (1.0f + erff(v0 * 0.70710678118654752f));
                v1 = 0.5f * v1 * (1.0f + erff(v1 * 0.70710678118654752f));
                v2 = 0.5f * v2 * (1.0f + erff(v2 * 0.70710678118654752f));
                v3 = 0.5f * v3 * (1.0f + erff(v3 * 0.70710678118654752f));
            }
            if (EPI == 0 || EPI == 2) {
                *(__half2*)&Ch[o0] = __floats2half2_rn(v0, v1);
                *(__half2*)&Ch[o1] = __floats2half2_rn(v2, v3);
            } else {
                if (EPI == 3 || EPI == 4) {
                    float2 r0 = *(const float2*)(res + o0);
                    float2 r1 = *(const float2*)(res + o1);
                    v0 += r0.x; v1 += r0.y; v2 += r1.x; v3 += r1.y;
                }
                *(float2*)(C + o0) = make_float2(v0, v1);
                *(float2*)(C + o1) = make_float2(v2, v3);
            }
        }
    }
}

// -------- QK RMSNorm + 2D RoPE on interleaved half qkv ----------------------
__global__ void __launch_bounds__(256) qkrope_k(__half* __restrict__ QKV,
                                                const float* __restrict__ qg,
                                                const float* __restrict__ kg,
                                                const int* __restrict__ h_idx,
                                                const int* __restrict__ w_idx)
{
    int warp = blockIdx.x * 8 + (threadIdx.x >> 5);
    int lane = threadIdx.x & 31;
    int grp = warp / (Mrows * Hh);       // 0=Q, 1=K
    int rid = warp - grp * (Mrows * Hh);
    int bn = rid / Hh;
    int h  = rid % Hh;

    __half* ptr = QKV + (size_t)bn * 3 * DIMd + grp * DIMd + h * DHd;
    const float* g = (grp == 0 ? qg : kg) + h * DHd;

    float v1 = __half2float(ptr[lane]);
    float v2 = __half2float(ptr[lane + 32]);
    float ss = v1 * v1 + v2 * v2;
#pragma unroll
    for (int o = 16; o; o >>= 1) ss += __shfl_xor_sync(~0u, ss, o);
    float sc = 8.0f / fmaxf(sqrtf(ss), 1e-12f);
    v1 = v1 * sc * g[lane];
    v2 = v2 * sc * g[lane + 32];

    int f = lane & 15;
    float invf = exp2f(-(float)f * (13.287712379549449f / 16.0f));
    float th1 = (float)h_idx[bn] * invf;
    float th2 = (float)w_idx[bn] * invf;
    float p1 = __shfl_xor_sync(~0u, v1, 16);
    float p2 = __shfl_xor_sync(~0u, v2, 16);
    float rh1 = (lane < 16) ? -p1 : p1;
    float rh2 = (lane < 16) ? -p2 : p2;
    ptr[lane]      = __float2half_rn(v1 * cosf(th1) + rh1 * sinf(th1));
    ptr[lane + 32] = __float2half_rn(v2 * cosf(th2) + rh2 * sinf(th2));
}

// ---------------- fp16 TC flash attention ----------------------------------
// 256 threads = 8 warps x 16 q-rows, 64-key tiles, Q frags in registers,
// cp.async double-buffered K/V (half), ldmatrix.trans for V fragments.
#define KS_LDH 72   // halves per row (144B)
#define VS_LDH 72
#define PS_LDH 72
#define ATT_SMEM ((2*64*KS_LDH + 2*64*VS_LDH + 128*PS_LDH) * 2)   // 55296

__global__ void __launch_bounds__(256, 2) attn_tc(const __half* __restrict__ QKV,
                                                  const int* __restrict__ lengths,
                                                  __half* __restrict__ O)
{
    extern __shared__ __half smh[];
    __half* KsB = smh;                        // 2 x [64][KS_LDH]
    __half* VsB = KsB + 2 * 64 * KS_LDH;      // 2 x [64][VS_LDH]
    __half* Ps  = VsB + 2 * 64 * VS_LDH;      // [128][PS_LDH]
    uint32_t vs_base = cvta_s(VsB);

    int b = blockIdx.z, h = blockIdx.y, q0 = blockIdx.x * 128;
    int tid = threadIdx.x;
    int warp = tid >> 5, lane = tid & 31;
    int g = lane >> 2, t = lane & 3;
    int wq = warp * 16;

    const __half* Qg = QKV + ((size_t)b * Nn + q0) * 3 * DIMd + h * DHd;
    const __half* Kg = QKV + ((size_t)b * Nn) * 3 * DIMd + DIMd + h * DHd;
    int len = lengths[b];

    // Q fragments in registers
    uint32_t qf[4][4];
    {
        const __half* r0 = Qg + (size_t)(wq + g) * 3 * DIMd;
        const __half* r1 = r0 + (size_t)8 * 3 * DIMd;
#pragma unroll
        for (int ks = 0; ks < 4; ks++) {
            qf[ks][0] = *(const uint32_t*)&r0[ks * 16 + 2 * t];
            qf[ks][1] = *(const uint32_t*)&r1[ks * 16 + 2 * t];
            qf[ks][2] = *(const uint32_t*)&r0[ks * 16 + 2 * t + 8];
            qf[ks][3] = *(const uint32_t*)&r1[ks * 16 + 2 * t + 8];
        }
    }

    float Oa[8][4];
    float mrow[2], lrow[2];
#pragma unroll
    for (int n = 0; n < 8; n++)
#pragma unroll
        for (int c = 0; c < 4; c++) Oa[n][c] = 0.f;
    mrow[0] = mrow[1] = -1e30f;
    lrow[0] = lrow[1] = 0.f;

    int ntiles = (len + 63) >> 6;

    auto loadKV = [&](int buf, int kt) {
        uint32_t Kd = cvta_s(KsB) + (uint32_t)buf * (64 * KS_LDH * 2);
        uint32_t Vd = vs_base + (uint32_t)buf * (64 * VS_LDH * 2);
#pragma unroll
        for (int p = 0; p < 2; p++) {
            int idx = tid + p * 256;      // 512 chunks of 8 halves
            int r = idx >> 3, c8 = (idx & 7) << 3;
            const __half* kp = Kg + (size_t)(kt * 64 + r) * (3 * DIMd) + c8;
            CPA16(Kd + (uint32_t)r * (KS_LDH * 2) + (uint32_t)c8 * 2, kp);
            CPA16(Vd + (uint32_t)r * (VS_LDH * 2) + (uint32_t)c8 * 2, kp + DIMd);
        }
    };

    loadKV(0, 0); CPCOMMIT();

    for (int kt = 0; kt < ntiles; kt++) {
        CPWAIT0();
        __syncthreads();
        if (kt + 1 < ntiles) { loadKV((kt + 1) & 1, kt + 1); CPCOMMIT(); }
        const __half* Ks = KsB + (kt & 1) * 64 * KS_LDH;
        uint32_t Vsb = vs_base + (uint32_t)(kt & 1) * (64 * VS_LDH * 2);

        // S = Q K^T
        float S[8][4];
#pragma unroll
        for (int n = 0; n < 8; n++)
#pragma unroll
            for (int c = 0; c < 4; c++) S[n][c] = 0.f;

#pragma unroll
        for (int ks = 0; ks < 4; ks++) {
#pragma unroll
            for (int nt = 0; nt < 8; nt++) {
                int key = nt * 8 + g;
                uint32_t b0 = *(const uint32_t*)&Ks[key * KS_LDH + ks * 16 + 2 * t];
                uint32_t b1 = *(const uint32_t*)&Ks[key * KS_LDH + ks * 16 + 2 * t + 8];
                mma16(S[nt][0], S[nt][1], S[nt][2], S[nt][3],
                      qf[ks][0], qf[ks][1], qf[ks][2], qf[ks][3], b0, b1);
            }
        }

        // key mask
#pragma unroll
        for (int nt = 0; nt < 8; nt++) {
            int kc = kt * 64 + nt * 8 + 2 * t;
            if (kc >= len)     { S[nt][0] = -1e30f; S[nt][2] = -1e30f; }
            if (kc + 1 >= len) { S[nt][1] = -1e30f; S[nt][3] = -1e30f; }
        }

        // online softmax
#pragma unroll
        for (int half = 0; half < 2; half++) {
            int i0 = half * 2, i1 = half * 2 + 1;
            float rm = -1e30f;
#pragma unroll
            for (int nt = 0; nt < 8; nt++)
                rm = fmaxf(rm, fmaxf(S[nt][i0], S[nt][i1]));
            rm = fmaxf(rm, __shfl_xor_sync(~0u, rm, 1));
            rm = fmaxf(rm, __shfl_xor_sync(~0u, rm, 2));
            float mn = fmaxf(mrow[half], rm);
            float rs = 0.f;
#pragma unroll
            for (int nt = 0; nt < 8; nt++) {
                S[nt][i0] = __expf(S[nt][i0] - mn);
                S[nt][i1] = __expf(S[nt][i1] - mn);
                rs += S[nt][i0] + S[nt][i1];
            }
            rs += __shfl_xor_sync(~0u, rs, 1);
            rs += __shfl_xor_sync(~0u, rs, 2);
            float corr = __expf(mrow[half] - mn);
            lrow[half] = lrow[half] * corr + rs;
            mrow[half] = mn;
#pragma unroll
            for (int nt = 0; nt < 8; nt++) {
                Oa[nt][i0] *= corr;
                Oa[nt][i1] *= corr;
            }
        }

        // stage P as half (warp-private rows)
        {
            int r = wq + g;
#pragma unroll
            for (int nt = 0; nt < 8; nt++) {
                *(__half2*)&Ps[r * PS_LDH + nt * 8 + 2 * t] =
                    __floats2half2_rn(S[nt][0], S[nt][1]);
                *(__half2*)&Ps[(r + 8) * PS_LDH + nt * 8 + 2 * t] =
                    __floats2half2_rn(S[nt][2], S[nt][3]);
            }
        }
        __syncwarp();

        // O += P V  (V B-frags via ldmatrix.x4.trans)
#pragma unroll
        for (int ks = 0; ks < 4; ks++) {
            uint32_t a0 = *(const uint32_t*)&Ps[(wq + g) * PS_LDH + ks * 16 + 2 * t];
            uint32_t a1 = *(const uint32_t*)&Ps[(wq + 8 + g) * PS_LDH + ks * 16 + 2 * t];
            uint32_t a2 = *(const uint32_t*)&Ps[(wq + g) * PS_LDH + ks * 16 + 2 * t + 8];
            uint32_t a3 = *(const uint32_t*)&Ps[(wq + 8 + g) * PS_LDH + ks * 16 + 2 * t + 8];
#pragma unroll
            for (int np = 0; np < 4; np++) {
                int vrow = ks * 16 + (lane & 15);
                int vcol = np * 16 + ((lane >> 4) << 3);
                uint32_t addr = Vsb + (uint32_t)vrow * (VS_LDH * 2) + (uint32_t)vcol * 2;
                uint32_t b00, b01, b10, b11;
                ldmx4t(b00, b01, b10, b11, addr);
                mma16(Oa[np * 2][0], Oa[np * 2][1], Oa[np * 2][2], Oa[np * 2][3],
                      a0, a1, a2, a3, b00, b01);
                mma16(Oa[np * 2 + 1][0], Oa[np * 2 + 1][1], Oa[np * 2 + 1][2], Oa[np * 2 + 1][3],
                      a0, a1, a2, a3, b10, b11);
            }
        }
    }

    // write out (ao is only ever a GEMM A operand -> half)
    {
        int row0 = q0 + wq + g;
        float inv0 = 1.0f / lrow[0];
        float inv1 = 1.0f / lrow[1];
#pragma unroll
        for (int nt = 0; nt < 8; nt++) {
            int col = h * DHd + nt * 8 + 2 * t;
            size_t o0 = ((size_t)b * Nn + row0) * DIMd + col;
            size_t o1 = ((size_t)b * Nn + row0 + 8) * DIMd + col;
            *(__half2*)&O[o0] = __floats2half2_rn(Oa[nt][0] * inv0, Oa[nt][1] * inv0);
            *(__half2*)&O[o1] = __floats2half2_rn(Oa[nt][2] * inv1, Oa[nt][3] * inv1);
        }
    }
}

// ---------------- mask tail writer -----------------------------------------
__global__ void mask_k(const int* __restrict__ lengths, float* __restrict__ out)
{
    int i = blockIdx.x * blockDim.x + threadIdx.x;
    if (i < Bb * Nn) {
        int b = i / Nn, n = i % Nn;
        out[i] = (n < lengths[b]) ? 1.0f : 0.0f;
    }
}

// ---------------- host orchestration ---------------------------------------
extern "C" void kernel_launch(void* const* d_in, const int* in_sizes, int n_in,
                              void* d_out, int out_size)
{
    const float* patches    = (const float*)d_in[0];
    const float* pe_ln1_g   = (const float*)d_in[1];
    const float* pe_W       = (const float*)d_in[2];
    const float* pe_b       = (const float*)d_in[3];
    const float* pe_ln2_g   = (const float*)d_in[4];
    const float* attn_ln_g  = (const float*)d_in[5];
    const float* qn_g       = (const float*)d_in[6];
    const float* kn_g       = (const float*)d_in[7];
    const float* Wq         = (const float*)d_in[8];
    const float* Wkv        = (const float*)d_in[9];
    const float* Wo         = (const float*)d_in[10];
    const float* ff_ln_g    = (const float*)d_in[11];
    const float* W1         = (const float*)d_in[12];
    const float* b1         = (const float*)d_in[13];
    const float* W2         = (const float*)d_in[14];
    const float* b2         = (const float*)d_in[15];
    const float* final_ln_g = (const float*)d_in[16];
    const int*   h_idx      = (const int*)d_in[17];
    const int*   w_idx      = (const int*)d_in[18];
    const int*   lengths    = (const int*)d_in[19];

    float *x;
    __half *xn, *qkv, *ao, *hb, *wpk;
    cudaGetSymbolAddress((void**)&x,   g_x);
    cudaGetSymbolAddress((void**)&xn,  g_xn);
    cudaGetSymbolAddress((void**)&qkv, g_qkv);
    cudaGetSymbolAddress((void**)&ao,  g_ao);
    cudaGetSymbolAddress((void**)&hb,  g_h);
    cudaGetSymbolAddress((void**)&wpk, g_wpk);

    cudaFuncSetAttribute(gemm_tc<0>, cudaFuncAttributeMaxDynamicSharedMemorySize, GEMM_SMEM);
    cudaFuncSetAttribute(gemm_tc<1>, cudaFuncAttributeMaxDynamicSharedMemorySize, GEMM_SMEM);
    cudaFuncSetAttribute(gemm_tc<2>, cudaFuncAttributeMaxDynamicSharedMemorySize, GEMM_SMEM);
    cudaFuncSetAttribute(gemm_tc<3>, cudaFuncAttributeMaxDynamicSharedMemorySize, GEMM_SMEM);
    cudaFuncSetAttribute(gemm_tc<4>, cudaFuncAttributeMaxDynamicSharedMemorySize, GEMM_SMEM);
    cudaFuncSetAttribute(attn_tc, cudaFuncAttributeMaxDynamicSharedMemorySize, ATT_SMEM);

    dim3 t256(256);

    // ---- weight offsets inside g_wpk (halves) ------------------------------
    size_t off_pe = 0;
    size_t off_qkv[Ll], off_o[Ll], off_1[Ll], off_2[Ll];
    {
        size_t cur = (size_t)DIMd * DIMd;
        for (int i = 0; i < Ll; i++) {
            off_qkv[i] = cur; cur += (size_t)DIMd * 3 * DIMd;
            off_o  [i] = cur; cur += (size_t)DIMd * DIMd;
            off_1  [i] = cur; cur += (size_t)DIMd * MLPm;
            off_2  [i] = cur; cur += (size_t)MLPm * DIMd;
        }
    }

    PackTable tab;
    int ti = 0;
    tab.d[ti++] = { pe_W, wpk + off_pe, DIMd, DIMd, DIMd, 0 };
    for (int i = 0; i < Ll; i++) {
        tab.d[ti++] = { Wq  + (size_t)i * DIMd * DIMd,     wpk + off_qkv[i], DIMd, DIMd,     3 * DIMd, 0 };
        tab.d[ti++] = { Wkv + (size_t)i * DIMd * 2 * DIMd, wpk + off_qkv[i], DIMd, 2 * DIMd, 3 * DIMd, DIMd };
        tab.d[ti++] = { Wo  + (size_t)i * DIMd * DIMd,     wpk + off_o [i],  DIMd, DIMd,     DIMd, 0 };
        tab.d[ti++] = { W1  + (size_t)i * DIMd * MLPm,     wpk + off_1 [i],  DIMd, MLPm,     MLPm, 0 };
        tab.d[ti++] = { W2  + (size_t)i * MLPm * DIMd,     wpk + off_2 [i],  MLPm, DIMd,     DIMd, 0 };
    }
    pack_all<<<dim3(288, 11), t256>>>(tab);

    dim3 gLN(Mrows / 8);
    dim3 gN768(DIMd / 128, Mrows / 128);        // (6, 64)
    dim3 gN2304(3 * DIMd / 128, Mrows / 128);   // (18, 64)
    dim3 gN3072(MLPm / 128, Mrows / 128);       // (24, 64)

    // patch embedding: LN -> Linear+bias -> LN
    ln_w<1><<<gLN, t256>>>(patches, pe_ln1_g, xn);
    gemm_tc<1><<<gN768, t256, GEMM_SMEM>>>(xn, wpk + off_pe, pe_b, nullptr, x, DIMd, DIMd);
    ln_w<0><<<gLN, t256>>>(x, pe_ln2_g, x);

    for (int i = 0; i < Ll; i++) {
        ln_w<1><<<gLN, t256>>>(x, attn_ln_g + (size_t)i * DIMd, xn);
        gemm_tc<0><<<gN2304, t256, GEMM_SMEM>>>(xn, wpk + off_qkv[i], nullptr, nullptr,
                                                qkv, DIMd, 3 * DIMd);
        qkrope_k<<<(2 * Mrows * Hh) / 8, t256>>>(
            qkv, qn_g + (size_t)i * Hh * DHd, kn_g + (size_t)i * Hh * DHd,
            h_idx, w_idx);
        attn_tc<<<dim3(Nn / 128, Hh, Bb), t256, ATT_SMEM>>>(qkv, lengths, ao);
        gemm_tc<3><<<gN768, t256, GEMM_SMEM>>>(ao, wpk + off_o[i], nullptr, x, x, DIMd, DIMd);
        ln_w<1><<<gLN, t256>>>(x, ff_ln_g + (size_t)i * DIMd, xn);
        gemm_tc<2><<<gN3072, t256, GEMM_SMEM>>>(xn, wpk + off_1[i], b1 + (size_t)i * MLPm,
                                                nullptr, hb, DIMd, MLPm);
        gemm_tc<4><<<gN768, t256, GEMM_SMEM>>>(hb, wpk + off_2[i], b2 + (size_t)i * DIMd,
                                               x, x, MLPm, DIMd);
    }

    ln_w<0><<<gLN, t256>>>(x, final_ln_g, (float*)d_out);

    if (out_size > Mrows * DIMd) {
        mask_k<<<(Bb * Nn + 255) / 256, t256>>>(lengths,
                                                (float*)d_out + (size_t)Mrows * DIMd);
    }
}